// round 3
// baseline (speedup 1.0000x reference)
#include <cuda_runtime.h>
#include <math.h>

namespace {

constexpr int T   = 512;
constexpr int D   = 512;
constexpr int Bb  = 16;
constexpr int DT  = 16;          // d-tile per CTA
constexpr int NTH = 256;
constexpr int NTILES = D / DT;   // 32
constexpr int F   = 255;         // freq bins 1..255
constexpr float TWO_PI = 6.2831853071795864769f;

struct Smem {
    float  xs[T * DT];            // x, then x_rem (in place)
    float  cs[(T + 1) * DT];      // prefix sums of x_rem
    float  scratch[T * DT];       // phase1: Re/Im (255*16 float2); phase2+: season
    float2 tab[T];                // (cos, sin)(2*pi*j/512)
    float  wl[T];                 // W_lin
    float  wt[8], bt[8];          // W_trend, b_trend (6 used)
    int    selk[DT][4];           // selected freq index k (1..255)
    float  selRe[DT][4];
    float  selIm[DT][4];
    float  xr0[DT], xrL[DT];      // x_rem at t=0 and t=T-1 (edge replication)
    float  red[NTH];
};

__device__ float g_xtrans[Bb * D];

} // namespace

__global__ __launch_bounds__(NTH) void msr_main(
    const float* __restrict__ x,
    const float* __restrict__ wt_g,
    const float* __restrict__ bt_g,
    const float* __restrict__ wl_g,
    const float* __restrict__ bl_g)
{
    extern __shared__ unsigned char smem_raw[];
    Smem& sm = *reinterpret_cast<Smem*>(smem_raw);

    const int tid = threadIdx.x;
    const int b   = blockIdx.y;
    const int d0  = blockIdx.x * DT;

    // ---- init tables ----
    for (int j = tid; j < T; j += NTH) {
        float s, c;
        sincosf(TWO_PI * (float)j / (float)T, &s, &c);
        sm.tab[j] = make_float2(c, s);
        sm.wl[j]  = wl_g[j];
    }
    if (tid < 6) { sm.wt[tid] = wt_g[tid]; sm.bt[tid] = bt_g[tid]; }

    // ---- load x tile: xs[t*DT + dd] = x[b, t, d0+dd] ----
    {
        const float* xb = x + (size_t)b * T * D + d0;
        const int q = (tid & 3) * 4;
        const int t0 = tid >> 2;
        #pragma unroll
        for (int i = 0; i < 8; i++) {
            int t = t0 + 64 * i;
            float4 v = *reinterpret_cast<const float4*>(xb + (size_t)t * D + q);
            *reinterpret_cast<float4*>(&sm.xs[t * DT + q]) = v;
        }
    }
    __syncthreads();

    // ---- Phase 1: direct DFT, thread owns frequency f = tid+1 ----
    {
        const int f = tid + 1;                     // 1..256 (256 = Nyquist, discarded)
        const float2 w = sm.tab[f & (T - 1)];
        const float cw = w.x, sw = w.y;
        float cr = 1.f, si = 0.f;
        float accR[DT], accI[DT];
        #pragma unroll
        for (int dd = 0; dd < DT; dd++) { accR[dd] = 0.f; accI[dd] = 0.f; }

        for (int t = 0; t < T; t++) {
            if ((t & 63) == 0) {                   // resync twiddle from exact table
                float2 e = sm.tab[(f * t) & (T - 1)];
                cr = e.x; si = e.y;
            }
            float4 a0 = *reinterpret_cast<const float4*>(&sm.xs[t * DT + 0]);
            float4 a1 = *reinterpret_cast<const float4*>(&sm.xs[t * DT + 4]);
            float4 a2 = *reinterpret_cast<const float4*>(&sm.xs[t * DT + 8]);
            float4 a3 = *reinterpret_cast<const float4*>(&sm.xs[t * DT + 12]);
            accR[0]  = fmaf(a0.x,  cr, accR[0]);  accI[0]  = fmaf(-a0.x, si, accI[0]);
            accR[1]  = fmaf(a0.y,  cr, accR[1]);  accI[1]  = fmaf(-a0.y, si, accI[1]);
            accR[2]  = fmaf(a0.z,  cr, accR[2]);  accI[2]  = fmaf(-a0.z, si, accI[2]);
            accR[3]  = fmaf(a0.w,  cr, accR[3]);  accI[3]  = fmaf(-a0.w, si, accI[3]);
            accR[4]  = fmaf(a1.x,  cr, accR[4]);  accI[4]  = fmaf(-a1.x, si, accI[4]);
            accR[5]  = fmaf(a1.y,  cr, accR[5]);  accI[5]  = fmaf(-a1.y, si, accI[5]);
            accR[6]  = fmaf(a1.z,  cr, accR[6]);  accI[6]  = fmaf(-a1.z, si, accI[6]);
            accR[7]  = fmaf(a1.w,  cr, accR[7]);  accI[7]  = fmaf(-a1.w, si, accI[7]);
            accR[8]  = fmaf(a2.x,  cr, accR[8]);  accI[8]  = fmaf(-a2.x, si, accI[8]);
            accR[9]  = fmaf(a2.y,  cr, accR[9]);  accI[9]  = fmaf(-a2.y, si, accI[9]);
            accR[10] = fmaf(a2.z,  cr, accR[10]); accI[10] = fmaf(-a2.z, si, accI[10]);
            accR[11] = fmaf(a2.w,  cr, accR[11]); accI[11] = fmaf(-a2.w, si, accI[11]);
            accR[12] = fmaf(a3.x,  cr, accR[12]); accI[12] = fmaf(-a3.x, si, accI[12]);
            accR[13] = fmaf(a3.y,  cr, accR[13]); accI[13] = fmaf(-a3.y, si, accI[13]);
            accR[14] = fmaf(a3.z,  cr, accR[14]); accI[14] = fmaf(-a3.z, si, accI[14]);
            accR[15] = fmaf(a3.w,  cr, accR[15]); accI[15] = fmaf(-a3.w, si, accI[15]);
            float c2 = cr * cw - si * sw;
            si = fmaf(si, cw, cr * sw);
            cr = c2;
        }

        if (tid < F) {
            float2* ri = reinterpret_cast<float2*>(sm.scratch);
            #pragma unroll
            for (int dd = 0; dd < DT; dd++)
                ri[tid * DT + dd] = make_float2(accR[dd], accI[dd]);
        }
    }
    __syncthreads();

    // ---- Phase 1b: per-d top-4 |X|^2 (tie -> lower index, like lax.top_k) ----
    {
        const int lane = tid & 31, wid = tid >> 5;
        const float2* ri = reinterpret_cast<const float2*>(sm.scratch);
        for (int dd = wid * 2; dd < wid * 2 + 2; dd++) {
            int sel0 = -1, sel1 = -1, sel2 = -1, sel3 = -1;
            #pragma unroll
            for (int pass = 0; pass < 4; pass++) {
                float best = -1.f; int bi = 0x7fffffff;
                for (int r = lane; r < F; r += 32) {
                    if (r == sel0 || r == sel1 || r == sel2 || r == sel3) continue;
                    float2 v = ri[r * DT + dd];
                    float a = v.x * v.x + v.y * v.y;
                    if (a > best || (a == best && r < bi)) { best = a; bi = r; }
                }
                #pragma unroll
                for (int off = 16; off > 0; off >>= 1) {
                    float ob = __shfl_down_sync(0xffffffffu, best, off);
                    int   oi = __shfl_down_sync(0xffffffffu, bi,   off);
                    if (ob > best || (ob == best && oi < bi)) { best = ob; bi = oi; }
                }
                bi = __shfl_sync(0xffffffffu, bi, 0);
                if      (pass == 0) sel0 = bi;
                else if (pass == 1) sel1 = bi;
                else if (pass == 2) sel2 = bi;
                else                sel3 = bi;
            }
            if (lane == 0) {
                int s4[4] = { sel0, sel1, sel2, sel3 };
                #pragma unroll
                for (int j = 0; j < 4; j++) {
                    int r = s4[j];
                    float2 v = ri[r * DT + dd];
                    sm.selk[dd][j]  = r + 1;     // actual frequency index
                    sm.selRe[dd][j] = v.x;
                    sm.selIm[dd][j] = v.y;
                }
            }
        }
    }
    __syncthreads();

    // ---- Phase 2: season(t,d), x_rem = x - season (in place), store season ----
    {
        const float scale = 2.0f / (float)T;
        for (int idx = tid; idx < T * DT; idx += NTH) {
            int t = idx >> 4, dd = idx & 15;
            float se = 0.f;
            #pragma unroll
            for (int j = 0; j < 4; j++) {
                int k = sm.selk[dd][j];
                float2 e = sm.tab[(k * t) & (T - 1)];
                se = fmaf(sm.selRe[dd][j], e.x, se);
                se = fmaf(-sm.selIm[dd][j], e.y, se);
            }
            se *= scale;
            float xr = sm.xs[idx] - se;
            sm.xs[idx] = xr;
            sm.scratch[idx] = se;
            if (t == 0)     sm.xr0[dd] = xr;
            if (t == T - 1) sm.xrL[dd] = xr;
        }
    }
    __syncthreads();

    // ---- Phase 3: prefix sums of x_rem per d ----
    if (tid < DT) {
        float run = 0.f;
        sm.cs[tid] = 0.f;
        for (int t = 0; t < T; t++) {
            run += sm.xs[t * DT + tid];
            sm.cs[(t + 1) * DT + tid] = run;
        }
    }
    __syncthreads();

    // ---- Phase 4: moving averages + softmax blend + W_lin reduction ----
    {
        const int dd = tid & 15;
        const float x0 = sm.xr0[dd], xL = sm.xrL[dd];
        float wtr[6], btr[6];
        #pragma unroll
        for (int j = 0; j < 6; j++) { wtr[j] = sm.wt[j]; btr[j] = sm.bt[j]; }

        float acc = 0.f;
        const int tb = tid >> 4;
        #pragma unroll 4
        for (int i = 0; i < 32; i++) {
            int t = tb + 16 * i;
            float xr = sm.xs[t * DT + dd];
            float num = 0.f, den = 0.f;
            const int ksArr[6] = { 4, 8, 12, 16, 24, 32 };
            #pragma unroll
            for (int j = 0; j < 6; j++) {
                const int k = ksArr[j];
                const int h = k >> 1;
                int lo = t - h, hi = t + h - 1;
                int hiC = hi < (T - 1) ? hi : (T - 1);
                int loC = lo > 0 ? lo : 0;
                float s = sm.cs[(hiC + 1) * DT + dd] - sm.cs[loC * DT + dd];
                if (lo < 0)     s = fmaf((float)(-lo), x0, s);
                if (hi > T - 1) s = fmaf((float)(hi - (T - 1)), xL, s);
                float e = __expf(fmaf(xr, wtr[j], btr[j]));
                den += e;
                num = fmaf(s * (1.0f / (float)k), e, num);
            }
            float xsum = xr + 2.f * sm.scratch[t * DT + dd] + num / den;
            acc = fmaf(xsum, sm.wl[t], acc);
        }
        sm.red[tid] = acc;
    }
    __syncthreads();

    if (tid < DT) {
        float s = 0.f;
        #pragma unroll
        for (int j = 0; j < NTH / DT; j++) s += sm.red[tid + DT * j];
        g_xtrans[b * D + d0 + tid] = s + bl_g[0];
    }
}

__global__ __launch_bounds__(32) void msr_final(
    const float* __restrict__ noise,
    const float* __restrict__ Wr, const float* __restrict__ br,
    const float* __restrict__ Wn, const float* __restrict__ bn,
    float* __restrict__ out)
{
    const int b = blockIdx.x, lane = threadIdx.x;
    float aB[8], aN[8];
    #pragma unroll
    for (int m = 0; m < 8; m++) { aB[m] = 0.f; aN[m] = 0.f; }

    for (int d = lane; d < D; d += 32) {
        float xt = g_xtrans[b * D + d];
        #pragma unroll
        for (int m = 0; m < 8; m++) {
            aB[m] = fmaf(xt, Wr[d * 8 + m], aB[m]);
            aN[m] = fmaf(xt, Wn[d * 8 + m], aN[m]);
        }
    }
    #pragma unroll
    for (int m = 0; m < 8; m++) {
        #pragma unroll
        for (int off = 16; off > 0; off >>= 1) {
            aB[m] += __shfl_down_sync(0xffffffffu, aB[m], off);
            aN[m] += __shfl_down_sync(0xffffffffu, aN[m], off);
        }
    }
    if (lane == 0) {
        float pw[8];
        float mx = -1e30f;
        #pragma unroll
        for (int m = 0; m < 8; m++) {
            float z  = aN[m] + bn[m];
            float sp = (z > 20.f) ? z : log1pf(expf(z));   // softplus
            float l  = aB[m] + br[m] + noise[b * 8 + m] * sp;
            pw[m] = l;
            if (l > mx) mx = l;
        }
        float s = 0.f;
        #pragma unroll
        for (int m = 0; m < 8; m++) { pw[m] = expf(pw[m] - mx); s += pw[m]; }
        float inv = 1.f / s;
        #pragma unroll
        for (int m = 0; m < 8; m++) pw[m] *= inv;

        // top-4 of 8 (tie -> lower index); keep mask in a bitfield
        unsigned kept = 0u;
        #pragma unroll
        for (int p = 0; p < 4; p++) {
            float best = -1.f; int bi = 0;
            #pragma unroll
            for (int m = 0; m < 8; m++) {
                bool free_m = ((kept >> m) & 1u) == 0u;
                if (free_m && pw[m] > best) { best = pw[m]; bi = m; }
            }
            kept |= (1u << bi);
        }
        #pragma unroll
        for (int m = 0; m < 8; m++)
            out[b * 8 + m] = ((kept >> m) & 1u) ? pw[m] : 0.f;
    }
}

extern "C" void kernel_launch(void* const* d_in, const int* in_sizes, int n_in,
                              void* d_out, int out_size) {
    const float* x     = (const float*)d_in[0];
    const float* noise = (const float*)d_in[1];
    const float* Wr    = (const float*)d_in[2];
    const float* br    = (const float*)d_in[3];
    const float* Wn    = (const float*)d_in[4];
    const float* bn    = (const float*)d_in[5];
    const float* wt    = (const float*)d_in[6];
    const float* bt    = (const float*)d_in[7];
    const float* wl    = (const float*)d_in[8];
    const float* bl    = (const float*)d_in[9];
    float* out = (float*)d_out;

    (void)cudaFuncSetAttribute(msr_main, cudaFuncAttributeMaxDynamicSharedMemorySize,
                               (int)sizeof(Smem));
    dim3 grid(NTILES, Bb);
    msr_main<<<grid, NTH, sizeof(Smem)>>>(x, wt, bt, wl, bl);
    msr_final<<<Bb, 32>>>(noise, Wr, br, Wn, bn, out);
}

// round 4
// speedup vs baseline: 1.0898x; 1.0898x over previous
#include <cuda_runtime.h>
#include <math.h>

namespace {

constexpr int T   = 512;
constexpr int D   = 512;
constexpr int Bb  = 16;
constexpr int DT  = 16;          // d-tile per CTA
constexpr int NTH = 256;
constexpr int NTILES = D / DT;   // 32
constexpr int F   = 255;         // freq bins 1..255
constexpr float TWO_PI = 6.2831853071795864769f;

struct Smem {
    float  xs[T * DT];            // x, then x_rem (in place)
    float  cs[(T + 1) * DT];      // phase1: e[] (first 4096) + o[] (next 4096); phase3+: prefix sums
    float  scratch[T * DT];       // phase1: Re/Im (255*16 float2); phase2+: season
    float2 tab[T];                // (cos, sin)(2*pi*j/512)
    float  wl[T];                 // W_lin
    float  wt[8], bt[8];          // W_trend, b_trend (6 used)
    int    selk[DT][4];           // selected freq index k (1..255)
    float  selRe[DT][4];
    float  selIm[DT][4];
    float  xr0[DT], xrL[DT];      // x_rem at t=0 and t=T-1 (edge replication)
    float  red[NTH];
};

__device__ float g_xtrans[Bb * D];

} // namespace

__global__ __launch_bounds__(NTH) void msr_main(
    const float* __restrict__ x,
    const float* __restrict__ wt_g,
    const float* __restrict__ bt_g,
    const float* __restrict__ wl_g,
    const float* __restrict__ bl_g)
{
    extern __shared__ unsigned char smem_raw[];
    Smem& sm = *reinterpret_cast<Smem*>(smem_raw);

    const int tid = threadIdx.x;
    const int b   = blockIdx.y;
    const int d0  = blockIdx.x * DT;

    // ---- init tables ----
    for (int j = tid; j < T; j += NTH) {
        float s, c;
        sincosf(TWO_PI * (float)j / (float)T, &s, &c);
        sm.tab[j] = make_float2(c, s);
        sm.wl[j]  = wl_g[j];
    }
    if (tid < 6) { sm.wt[tid] = wt_g[tid]; sm.bt[tid] = bt_g[tid]; }

    // ---- load x tile: xs[t*DT + dd] = x[b, t, d0+dd] ----
    {
        const float* xb = x + (size_t)b * T * D + d0;
        const int q = (tid & 3) * 4;
        const int t0 = tid >> 2;
        #pragma unroll
        for (int i = 0; i < 8; i++) {
            int t = t0 + 64 * i;
            float4 v = *reinterpret_cast<const float4*>(xb + (size_t)t * D + q);
            *reinterpret_cast<float4*>(&sm.xs[t * DT + q]) = v;
        }
    }
    __syncthreads();

    // ---- Phase 1a: even/odd precompute (real-input symmetry) ----
    // e[t] = x[t] + x[512-t], o[t] = x[t] - x[512-t], t = 1..255
    {
        float* ce = sm.cs;                 // indices t*16+dd, t=1..255
        float* co = sm.cs + 4096;
        for (int idx = tid; idx < 255 * DT; idx += NTH) {
            int t = (idx >> 4) + 1, dd = idx & 15;
            float a  = sm.xs[t * DT + dd];
            float bb = sm.xs[(T - t) * DT + dd];
            ce[t * DT + dd] = a + bb;
            co[t * DT + dd] = a - bb;
        }
    }
    __syncthreads();

    // ---- Phase 1: half-range DFT, thread owns frequency f = tid+1 ----
    {
        const int f = tid + 1;                     // 1..256 (256 = Nyquist, discarded)
        const float* ce = sm.cs;
        const float* co = sm.cs + 4096;
        const float2 w = sm.tab[f & (T - 1)];
        const float cw = w.x, sw = w.y;
        float cr, si;
        float accR[DT], accI[DT];
        const float sgn = (f & 1) ? -1.f : 1.f;    // (-1)^f for t=256 term
        #pragma unroll
        for (int q = 0; q < 4; q++) {
            float4 v0  = *reinterpret_cast<const float4*>(&sm.xs[0 * DT + q * 4]);
            float4 v256 = *reinterpret_cast<const float4*>(&sm.xs[256 * DT + q * 4]);
            accR[q*4+0] = fmaf(sgn, v256.x, v0.x);
            accR[q*4+1] = fmaf(sgn, v256.y, v0.y);
            accR[q*4+2] = fmaf(sgn, v256.z, v0.z);
            accR[q*4+3] = fmaf(sgn, v256.w, v0.w);
            accI[q*4+0] = 0.f; accI[q*4+1] = 0.f; accI[q*4+2] = 0.f; accI[q*4+3] = 0.f;
        }

        for (int t = 1; t < 256; t++) {
            if ((t & 63) == 0 || t == 1) {         // resync twiddle from exact table
                float2 e = sm.tab[(f * t) & (T - 1)];
                cr = e.x; si = e.y;
            }
            float4 e0 = *reinterpret_cast<const float4*>(&ce[t * DT + 0]);
            float4 e1 = *reinterpret_cast<const float4*>(&ce[t * DT + 4]);
            float4 e2 = *reinterpret_cast<const float4*>(&ce[t * DT + 8]);
            float4 e3 = *reinterpret_cast<const float4*>(&ce[t * DT + 12]);
            float4 o0 = *reinterpret_cast<const float4*>(&co[t * DT + 0]);
            float4 o1 = *reinterpret_cast<const float4*>(&co[t * DT + 4]);
            float4 o2 = *reinterpret_cast<const float4*>(&co[t * DT + 8]);
            float4 o3 = *reinterpret_cast<const float4*>(&co[t * DT + 12]);
            accR[0]  = fmaf(e0.x,  cr, accR[0]);  accI[0]  = fmaf(-o0.x, si, accI[0]);
            accR[1]  = fmaf(e0.y,  cr, accR[1]);  accI[1]  = fmaf(-o0.y, si, accI[1]);
            accR[2]  = fmaf(e0.z,  cr, accR[2]);  accI[2]  = fmaf(-o0.z, si, accI[2]);
            accR[3]  = fmaf(e0.w,  cr, accR[3]);  accI[3]  = fmaf(-o0.w, si, accI[3]);
            accR[4]  = fmaf(e1.x,  cr, accR[4]);  accI[4]  = fmaf(-o1.x, si, accI[4]);
            accR[5]  = fmaf(e1.y,  cr, accR[5]);  accI[5]  = fmaf(-o1.y, si, accI[5]);
            accR[6]  = fmaf(e1.z,  cr, accR[6]);  accI[6]  = fmaf(-o1.z, si, accI[6]);
            accR[7]  = fmaf(e1.w,  cr, accR[7]);  accI[7]  = fmaf(-o1.w, si, accI[7]);
            accR[8]  = fmaf(e2.x,  cr, accR[8]);  accI[8]  = fmaf(-o2.x, si, accI[8]);
            accR[9]  = fmaf(e2.y,  cr, accR[9]);  accI[9]  = fmaf(-o2.y, si, accI[9]);
            accR[10] = fmaf(e2.z,  cr, accR[10]); accI[10] = fmaf(-o2.z, si, accI[10]);
            accR[11] = fmaf(e2.w,  cr, accR[11]); accI[11] = fmaf(-o2.w, si, accI[11]);
            accR[12] = fmaf(e3.x,  cr, accR[12]); accI[12] = fmaf(-o3.x, si, accI[12]);
            accR[13] = fmaf(e3.y,  cr, accR[13]); accI[13] = fmaf(-o3.y, si, accI[13]);
            accR[14] = fmaf(e3.z,  cr, accR[14]); accI[14] = fmaf(-o3.z, si, accI[14]);
            accR[15] = fmaf(e3.w,  cr, accR[15]); accI[15] = fmaf(-o3.w, si, accI[15]);
            float c2 = cr * cw - si * sw;
            si = fmaf(si, cw, cr * sw);
            cr = c2;
        }

        if (tid < F) {
            float2* ri = reinterpret_cast<float2*>(sm.scratch);
            #pragma unroll
            for (int dd = 0; dd < DT; dd++)
                ri[tid * DT + dd] = make_float2(accR[dd], accI[dd]);
        }
    }
    __syncthreads();

    // ---- Phase 1b: per-d top-4 |X|^2 (tie -> lower index, like lax.top_k) ----
    {
        const int lane = tid & 31, wid = tid >> 5;
        const float2* ri = reinterpret_cast<const float2*>(sm.scratch);
        for (int dd = wid * 2; dd < wid * 2 + 2; dd++) {
            int sel0 = -1, sel1 = -1, sel2 = -1, sel3 = -1;
            #pragma unroll
            for (int pass = 0; pass < 4; pass++) {
                float best = -1.f; int bi = 0x7fffffff;
                for (int r = lane; r < F; r += 32) {
                    if (r == sel0 || r == sel1 || r == sel2 || r == sel3) continue;
                    float2 v = ri[r * DT + dd];
                    float a = v.x * v.x + v.y * v.y;
                    if (a > best || (a == best && r < bi)) { best = a; bi = r; }
                }
                #pragma unroll
                for (int off = 16; off > 0; off >>= 1) {
                    float ob = __shfl_down_sync(0xffffffffu, best, off);
                    int   oi = __shfl_down_sync(0xffffffffu, bi,   off);
                    if (ob > best || (ob == best && oi < bi)) { best = ob; bi = oi; }
                }
                bi = __shfl_sync(0xffffffffu, bi, 0);
                if      (pass == 0) sel0 = bi;
                else if (pass == 1) sel1 = bi;
                else if (pass == 2) sel2 = bi;
                else                sel3 = bi;
            }
            if (lane == 0) {
                int s4[4] = { sel0, sel1, sel2, sel3 };
                #pragma unroll
                for (int j = 0; j < 4; j++) {
                    int r = s4[j];
                    float2 v = ri[r * DT + dd];
                    sm.selk[dd][j]  = r + 1;     // actual frequency index
                    sm.selRe[dd][j] = v.x;
                    sm.selIm[dd][j] = v.y;
                }
            }
        }
    }
    __syncthreads();

    // ---- Phase 2: season(t,d), x_rem = x - season (in place), store season ----
    {
        const float scale = 2.0f / (float)T;
        for (int idx = tid; idx < T * DT; idx += NTH) {
            int t = idx >> 4, dd = idx & 15;
            float se = 0.f;
            #pragma unroll
            for (int j = 0; j < 4; j++) {
                int k = sm.selk[dd][j];
                float2 e = sm.tab[(k * t) & (T - 1)];
                se = fmaf(sm.selRe[dd][j], e.x, se);
                se = fmaf(-sm.selIm[dd][j], e.y, se);
            }
            se *= scale;
            float xr = sm.xs[idx] - se;
            sm.xs[idx] = xr;
            sm.scratch[idx] = se;
            if (t == 0)     sm.xr0[dd] = xr;
            if (t == T - 1) sm.xrL[dd] = xr;
        }
    }
    __syncthreads();

    // ---- Phase 3: prefix sums of x_rem per d ----
    if (tid < DT) {
        float run = 0.f;
        sm.cs[tid] = 0.f;
        for (int t = 0; t < T; t++) {
            run += sm.xs[t * DT + tid];
            sm.cs[(t + 1) * DT + tid] = run;
        }
    }
    __syncthreads();

    // ---- Phase 4: moving averages + softmax blend + W_lin reduction ----
    {
        const int dd = tid & 15;
        const float x0 = sm.xr0[dd], xL = sm.xrL[dd];
        float wtr[6], btr[6];
        #pragma unroll
        for (int j = 0; j < 6; j++) { wtr[j] = sm.wt[j]; btr[j] = sm.bt[j]; }

        float acc = 0.f;
        const int tb = tid >> 4;
        #pragma unroll 4
        for (int i = 0; i < 32; i++) {
            int t = tb + 16 * i;
            float xr = sm.xs[t * DT + dd];
            float num = 0.f, den = 0.f;
            const int ksArr[6] = { 4, 8, 12, 16, 24, 32 };
            #pragma unroll
            for (int j = 0; j < 6; j++) {
                const int k = ksArr[j];
                const int h = k >> 1;
                int lo = t - h, hi = t + h - 1;
                int hiC = hi < (T - 1) ? hi : (T - 1);
                int loC = lo > 0 ? lo : 0;
                float s = sm.cs[(hiC + 1) * DT + dd] - sm.cs[loC * DT + dd];
                if (lo < 0)     s = fmaf((float)(-lo), x0, s);
                if (hi > T - 1) s = fmaf((float)(hi - (T - 1)), xL, s);
                float e = __expf(fmaf(xr, wtr[j], btr[j]));
                den += e;
                num = fmaf(s * (1.0f / (float)k), e, num);
            }
            float xsum = xr + 2.f * sm.scratch[t * DT + dd] + num / den;
            acc = fmaf(xsum, sm.wl[t], acc);
        }
        sm.red[tid] = acc;
    }
    __syncthreads();

    if (tid < DT) {
        float s = 0.f;
        #pragma unroll
        for (int j = 0; j < NTH / DT; j++) s += sm.red[tid + DT * j];
        g_xtrans[b * D + d0 + tid] = s + bl_g[0];
    }
}

__global__ __launch_bounds__(256) void msr_final(
    const float* __restrict__ noise,
    const float* __restrict__ Wr, const float* __restrict__ br,
    const float* __restrict__ Wn, const float* __restrict__ bn,
    float* __restrict__ out)
{
    const int b = blockIdx.x;
    const int tid = threadIdx.x, lane = tid & 31, wid = tid >> 5;
    __shared__ float wacc[8][16];    // [warp][0..7 aB, 8..15 aN]
    __shared__ float fin[16];

    float aB[8], aN[8];
    #pragma unroll
    for (int m = 0; m < 8; m++) { aB[m] = 0.f; aN[m] = 0.f; }

    #pragma unroll
    for (int rep = 0; rep < 2; rep++) {
        int d = tid + rep * 256;
        float xt = g_xtrans[b * D + d];
        float4 r0 = *reinterpret_cast<const float4*>(Wr + d * 8);
        float4 r1 = *reinterpret_cast<const float4*>(Wr + d * 8 + 4);
        float4 n0 = *reinterpret_cast<const float4*>(Wn + d * 8);
        float4 n1 = *reinterpret_cast<const float4*>(Wn + d * 8 + 4);
        aB[0] = fmaf(xt, r0.x, aB[0]); aB[1] = fmaf(xt, r0.y, aB[1]);
        aB[2] = fmaf(xt, r0.z, aB[2]); aB[3] = fmaf(xt, r0.w, aB[3]);
        aB[4] = fmaf(xt, r1.x, aB[4]); aB[5] = fmaf(xt, r1.y, aB[5]);
        aB[6] = fmaf(xt, r1.z, aB[6]); aB[7] = fmaf(xt, r1.w, aB[7]);
        aN[0] = fmaf(xt, n0.x, aN[0]); aN[1] = fmaf(xt, n0.y, aN[1]);
        aN[2] = fmaf(xt, n0.z, aN[2]); aN[3] = fmaf(xt, n0.w, aN[3]);
        aN[4] = fmaf(xt, n1.x, aN[4]); aN[5] = fmaf(xt, n1.y, aN[5]);
        aN[6] = fmaf(xt, n1.z, aN[6]); aN[7] = fmaf(xt, n1.w, aN[7]);
    }
    #pragma unroll
    for (int m = 0; m < 8; m++) {
        #pragma unroll
        for (int off = 16; off > 0; off >>= 1) {
            aB[m] += __shfl_down_sync(0xffffffffu, aB[m], off);
            aN[m] += __shfl_down_sync(0xffffffffu, aN[m], off);
        }
    }
    if (lane == 0) {
        #pragma unroll
        for (int m = 0; m < 8; m++) { wacc[wid][m] = aB[m]; wacc[wid][m + 8] = aN[m]; }
    }
    __syncthreads();
    if (tid < 16) {
        float s = 0.f;
        #pragma unroll
        for (int w = 0; w < 8; w++) s += wacc[w][tid];
        fin[tid] = s;
    }
    __syncthreads();

    if (tid == 0) {
        float pw[8];
        float mx = -1e30f;
        #pragma unroll
        for (int m = 0; m < 8; m++) {
            float z  = fin[m + 8] + bn[m];
            float sp = (z > 20.f) ? z : log1pf(expf(z));   // softplus
            float l  = fin[m] + br[m] + noise[b * 8 + m] * sp;
            pw[m] = l;
            if (l > mx) mx = l;
        }
        float s = 0.f;
        #pragma unroll
        for (int m = 0; m < 8; m++) { pw[m] = expf(pw[m] - mx); s += pw[m]; }
        float inv = 1.f / s;
        #pragma unroll
        for (int m = 0; m < 8; m++) pw[m] *= inv;

        // top-4 of 8 (tie -> lower index); keep mask in a bitfield
        unsigned kept = 0u;
        #pragma unroll
        for (int p = 0; p < 4; p++) {
            float best = -1.f; int bi = 0;
            #pragma unroll
            for (int m = 0; m < 8; m++) {
                bool free_m = ((kept >> m) & 1u) == 0u;
                if (free_m && pw[m] > best) { best = pw[m]; bi = m; }
            }
            kept |= (1u << bi);
        }
        #pragma unroll
        for (int m = 0; m < 8; m++)
            out[b * 8 + m] = ((kept >> m) & 1u) ? pw[m] : 0.f;
    }
}

extern "C" void kernel_launch(void* const* d_in, const int* in_sizes, int n_in,
                              void* d_out, int out_size) {
    const float* x     = (const float*)d_in[0];
    const float* noise = (const float*)d_in[1];
    const float* Wr    = (const float*)d_in[2];
    const float* br    = (const float*)d_in[3];
    const float* Wn    = (const float*)d_in[4];
    const float* bn    = (const float*)d_in[5];
    const float* wt    = (const float*)d_in[6];
    const float* bt    = (const float*)d_in[7];
    const float* wl    = (const float*)d_in[8];
    const float* bl    = (const float*)d_in[9];
    float* out = (float*)d_out;

    (void)cudaFuncSetAttribute(msr_main, cudaFuncAttributeMaxDynamicSharedMemorySize,
                               (int)sizeof(Smem));
    dim3 grid(NTILES, Bb);
    msr_main<<<grid, NTH, sizeof(Smem)>>>(x, wt, bt, wl, bl);
    msr_final<<<Bb, 256>>>(noise, Wr, br, Wn, bn, out);
}

// round 5
// speedup vs baseline: 1.1371x; 1.0434x over previous
#include <cuda_runtime.h>
#include <math.h>

namespace {

constexpr int T   = 512;
constexpr int D   = 512;
constexpr int Bb  = 16;
constexpr int DT  = 16;          // d-tile per CTA
constexpr int NTH = 256;
constexpr int NTILES = D / DT;   // 32
constexpr int NCTA = NTILES * Bb; // 512
constexpr int F   = 255;         // freq bins 1..255
constexpr float TWO_PI = 6.2831853071795864769f;

struct alignas(16) ULL2 { unsigned long long x, y; };

struct Smem {
    float  xs[T * DT];            // x, then x_rem (in place)
    float  cs[(T + 1) * DT];      // phase1: e[] (first 4096) + o[] (next 4096); phase3+: prefix sums
    float  scratch[T * DT];       // phase1: Re/Im (255*16 float2); phase2+: season
    float2 tab[T];                // (cos, sin)(2*pi*j/512)
    float  wl[T];                 // W_lin
    float  wt[8], bt[8];          // W_trend, b_trend (6 used)
    int    selk[DT][4];           // selected freq index k (1..255)
    float  selRe[DT][4];
    float  selIm[DT][4];
    float  xr0[DT], xrL[DT];      // x_rem at t=0 and t=T-1 (edge replication)
    float  red[NTH];
    int    done_flag;
};

__device__ float g_xtrans[Bb * D];
__device__ unsigned int g_arrive = 0;

} // namespace

#define FMA2(d, a, b, c) asm("fma.rn.f32x2 %0, %1, %2, %3;" : "=l"(d) : "l"(a), "l"(b), "l"(c))
#define PACK2(d, x)      asm("mov.b64 %0, {%1, %1};" : "=l"(d) : "f"(x))
#define PACK2二(d, lo, hi) asm("mov.b64 %0, {%1, %2};" : "=l"(d) : "f"(lo), "f"(hi))
#define UNPACK2(lo, hi, s) asm("mov.b64 {%0, %1}, %2;" : "=f"(lo), "=f"(hi) : "l"(s))

__global__ __launch_bounds__(NTH) void msr_main(
    const float* __restrict__ x,
    const float* __restrict__ wt_g,
    const float* __restrict__ bt_g,
    const float* __restrict__ wl_g,
    const float* __restrict__ bl_g,
    const float* __restrict__ noise,
    const float* __restrict__ Wr, const float* __restrict__ br,
    const float* __restrict__ Wn, const float* __restrict__ bn,
    float* __restrict__ out)
{
    extern __shared__ unsigned char smem_raw[];
    Smem& sm = *reinterpret_cast<Smem*>(smem_raw);

    const int tid = threadIdx.x;
    const int b   = blockIdx.y;
    const int d0  = blockIdx.x * DT;

    // ---- init tables ----
    for (int j = tid; j < T; j += NTH) {
        float s, c;
        sincosf(TWO_PI * (float)j / (float)T, &s, &c);
        sm.tab[j] = make_float2(c, s);
        sm.wl[j]  = wl_g[j];
    }
    if (tid < 6) { sm.wt[tid] = wt_g[tid]; sm.bt[tid] = bt_g[tid]; }

    // ---- load x tile: xs[t*DT + dd] = x[b, t, d0+dd] ----
    {
        const float* xb = x + (size_t)b * T * D + d0;
        const int q = (tid & 3) * 4;
        const int t0 = tid >> 2;
        #pragma unroll
        for (int i = 0; i < 8; i++) {
            int t = t0 + 64 * i;
            float4 v = *reinterpret_cast<const float4*>(xb + (size_t)t * D + q);
            *reinterpret_cast<float4*>(&sm.xs[t * DT + q]) = v;
        }
    }
    __syncthreads();

    // ---- Phase 1a: even/odd precompute (real-input symmetry) ----
    {
        float* ce = sm.cs;
        float* co = sm.cs + 4096;
        for (int idx = tid; idx < 255 * DT; idx += NTH) {
            int t = (idx >> 4) + 1, dd = idx & 15;
            float a  = sm.xs[t * DT + dd];
            float bb = sm.xs[(T - t) * DT + dd];
            ce[t * DT + dd] = a + bb;
            co[t * DT + dd] = a - bb;
        }
    }
    __syncthreads();

    // ---- Phase 1: half-range DFT with packed f32x2 FMA; thread owns f = tid+1 ----
    {
        const int f = tid + 1;
        const float* ce = sm.cs;
        const float* co = sm.cs + 4096;
        const float2 w = sm.tab[f & (T - 1)];
        const float cw = w.x, sw = w.y;
        unsigned long long accR2[8], accI2[8];
        const float sgn = (f & 1) ? -1.f : 1.f;
        #pragma unroll
        for (int q = 0; q < 8; q++) {
            float2 v0 = *reinterpret_cast<const float2*>(&sm.xs[0 * DT + q * 2]);
            float2 v2 = *reinterpret_cast<const float2*>(&sm.xs[256 * DT + q * 2]);
            float lo = fmaf(sgn, v2.x, v0.x);
            float hi = fmaf(sgn, v2.y, v0.y);
            PACK2二(accR2[q], lo, hi);
            accI2[q] = 0ull;
        }

        float cr = 1.f, si = 0.f;
        #pragma unroll 1
        for (int blk = 0; blk < 4; blk++) {
            const int tstart = (blk == 0) ? 1 : blk * 64;
            const int tend   = blk * 64 + 64;
            { float2 e = sm.tab[(f * tstart) & (T - 1)]; cr = e.x; si = e.y; }
            #pragma unroll 2
            for (int t = tstart; t < tend; t++) {
                unsigned long long cr2, nsi2;
                PACK2(cr2, cr);
                float nsi = -si;
                PACK2(nsi2, nsi);
                const ULL2* ep = reinterpret_cast<const ULL2*>(&ce[t * DT]);
                const ULL2* op = reinterpret_cast<const ULL2*>(&co[t * DT]);
                ULL2 e0 = ep[0], e1 = ep[1], e2 = ep[2], e3 = ep[3];
                ULL2 o0 = op[0], o1 = op[1], o2 = op[2], o3 = op[3];
                FMA2(accR2[0], e0.x, cr2, accR2[0]);  FMA2(accI2[0], o0.x, nsi2, accI2[0]);
                FMA2(accR2[1], e0.y, cr2, accR2[1]);  FMA2(accI2[1], o0.y, nsi2, accI2[1]);
                FMA2(accR2[2], e1.x, cr2, accR2[2]);  FMA2(accI2[2], o1.x, nsi2, accI2[2]);
                FMA2(accR2[3], e1.y, cr2, accR2[3]);  FMA2(accI2[3], o1.y, nsi2, accI2[3]);
                FMA2(accR2[4], e2.x, cr2, accR2[4]);  FMA2(accI2[4], o2.x, nsi2, accI2[4]);
                FMA2(accR2[5], e2.y, cr2, accR2[5]);  FMA2(accI2[5], o2.y, nsi2, accI2[5]);
                FMA2(accR2[6], e3.x, cr2, accR2[6]);  FMA2(accI2[6], o3.x, nsi2, accI2[6]);
                FMA2(accR2[7], e3.y, cr2, accR2[7]);  FMA2(accI2[7], o3.y, nsi2, accI2[7]);
                float c2 = cr * cw - si * sw;
                si = fmaf(si, cw, cr * sw);
                cr = c2;
            }
        }

        if (tid < F) {
            float2* ri = reinterpret_cast<float2*>(sm.scratch);
            #pragma unroll
            for (int q = 0; q < 8; q++) {
                float rlo, rhi, ilo, ihi;
                UNPACK2(rlo, rhi, accR2[q]);
                UNPACK2(ilo, ihi, accI2[q]);
                ri[tid * DT + q * 2 + 0] = make_float2(rlo, ilo);
                ri[tid * DT + q * 2 + 1] = make_float2(rhi, ihi);
            }
        }
    }
    __syncthreads();

    // ---- Phase 1b: per-d top-4 |X|^2 (tie -> lower index) ----
    {
        const int lane = tid & 31, wid = tid >> 5;
        const float2* ri = reinterpret_cast<const float2*>(sm.scratch);
        for (int dd = wid * 2; dd < wid * 2 + 2; dd++) {
            int sel0 = -1, sel1 = -1, sel2 = -1, sel3 = -1;
            #pragma unroll
            for (int pass = 0; pass < 4; pass++) {
                float best = -1.f; int bi = 0x7fffffff;
                for (int r = lane; r < F; r += 32) {
                    if (r == sel0 || r == sel1 || r == sel2 || r == sel3) continue;
                    float2 v = ri[r * DT + dd];
                    float a = v.x * v.x + v.y * v.y;
                    if (a > best || (a == best && r < bi)) { best = a; bi = r; }
                }
                #pragma unroll
                for (int off = 16; off > 0; off >>= 1) {
                    float ob = __shfl_down_sync(0xffffffffu, best, off);
                    int   oi = __shfl_down_sync(0xffffffffu, bi,   off);
                    if (ob > best || (ob == best && oi < bi)) { best = ob; bi = oi; }
                }
                bi = __shfl_sync(0xffffffffu, bi, 0);
                if      (pass == 0) sel0 = bi;
                else if (pass == 1) sel1 = bi;
                else if (pass == 2) sel2 = bi;
                else                sel3 = bi;
            }
            if (lane == 0) {
                int s4[4] = { sel0, sel1, sel2, sel3 };
                #pragma unroll
                for (int j = 0; j < 4; j++) {
                    int r = s4[j];
                    float2 v = ri[r * DT + dd];
                    sm.selk[dd][j]  = r + 1;
                    sm.selRe[dd][j] = v.x;
                    sm.selIm[dd][j] = v.y;
                }
            }
        }
    }
    __syncthreads();

    // ---- Phase 2: season, x_rem = x - season (in place), store season ----
    {
        const float scale = 2.0f / (float)T;
        for (int idx = tid; idx < T * DT; idx += NTH) {
            int t = idx >> 4, dd = idx & 15;
            float se = 0.f;
            #pragma unroll
            for (int j = 0; j < 4; j++) {
                int k = sm.selk[dd][j];
                float2 e = sm.tab[(k * t) & (T - 1)];
                se = fmaf(sm.selRe[dd][j], e.x, se);
                se = fmaf(-sm.selIm[dd][j], e.y, se);
            }
            se *= scale;
            float xr = sm.xs[idx] - se;
            sm.xs[idx] = xr;
            sm.scratch[idx] = se;
            if (t == 0)     sm.xr0[dd] = xr;
            if (t == T - 1) sm.xrL[dd] = xr;
        }
    }
    __syncthreads();

    // ---- Phase 3: segmented parallel prefix sums of x_rem per d ----
    {
        const int dd = tid & 15, seg = tid >> 4;
        const int t0 = seg * 32;
        float s = 0.f;
        #pragma unroll
        for (int i = 0; i < 32; i++) s += sm.xs[(t0 + i) * DT + dd];
        sm.red[seg * 16 + dd] = s;
    }
    __syncthreads();
    if (tid < 16) {
        float run = 0.f;
        #pragma unroll
        for (int sgi = 0; sgi < 16; sgi++) {
            float v = sm.red[sgi * 16 + tid];
            sm.red[sgi * 16 + tid] = run;
            run += v;
        }
    }
    __syncthreads();
    {
        const int dd = tid & 15, seg = tid >> 4;
        const int t0 = seg * 32;
        float run = sm.red[seg * 16 + dd];
        if (seg == 0) sm.cs[dd] = 0.f;
        #pragma unroll
        for (int i = 0; i < 32; i++) {
            run += sm.xs[(t0 + i) * DT + dd];
            sm.cs[(t0 + i + 1) * DT + dd] = run;
        }
    }
    __syncthreads();

    // ---- Phase 4: moving averages + softmax blend + W_lin reduction ----
    {
        const int dd = tid & 15;
        const float x0 = sm.xr0[dd], xL = sm.xrL[dd];
        float wtr[6], btr[6];
        #pragma unroll
        for (int j = 0; j < 6; j++) { wtr[j] = sm.wt[j]; btr[j] = sm.bt[j]; }

        float acc = 0.f;
        const int tb = tid >> 4;
        #pragma unroll 4
        for (int i = 0; i < 32; i++) {
            int t = tb + 16 * i;
            float xr = sm.xs[t * DT + dd];
            float num = 0.f, den = 0.f;
            const int ksArr[6] = { 4, 8, 12, 16, 24, 32 };
            #pragma unroll
            for (int j = 0; j < 6; j++) {
                const int k = ksArr[j];
                const int h = k >> 1;
                int lo = t - h, hi = t + h - 1;
                int hiC = hi < (T - 1) ? hi : (T - 1);
                int loC = lo > 0 ? lo : 0;
                float s = sm.cs[(hiC + 1) * DT + dd] - sm.cs[loC * DT + dd];
                if (lo < 0)     s = fmaf((float)(-lo), x0, s);
                if (hi > T - 1) s = fmaf((float)(hi - (T - 1)), xL, s);
                float e = __expf(fmaf(xr, wtr[j], btr[j]));
                den += e;
                num = fmaf(s * (1.0f / (float)k), e, num);
            }
            float xsum = xr + 2.f * sm.scratch[t * DT + dd] + num / den;
            acc = fmaf(xsum, sm.wl[t], acc);
        }
        sm.red[tid] = acc;
    }
    __syncthreads();

    if (tid < DT) {
        float s = 0.f;
        #pragma unroll
        for (int j = 0; j < NTH / DT; j++) s += sm.red[tid + DT * j];
        g_xtrans[b * D + d0 + tid] = s + bl_g[0];
        __threadfence();
    }
    __syncthreads();

    // ---- Fused finalize: last CTA does router head for all 16 b ----
    if (tid == 0) {
        unsigned int old = atomicAdd(&g_arrive, 1u);
        sm.done_flag = (old == (unsigned)(NCTA - 1)) ? 1 : 0;
    }
    __syncthreads();
    if (sm.done_flag) {
        __threadfence();
        const int lane = tid & 31, wid = tid >> 5;
        #pragma unroll 1
        for (int rep = 0; rep < 2; rep++) {
            const int bb = wid * 2 + rep;
            float aB[8], aN[8];
            #pragma unroll
            for (int m = 0; m < 8; m++) { aB[m] = 0.f; aN[m] = 0.f; }
            for (int d = lane; d < D; d += 32) {
                float xt = g_xtrans[bb * D + d];
                float4 r0 = *reinterpret_cast<const float4*>(Wr + d * 8);
                float4 r1 = *reinterpret_cast<const float4*>(Wr + d * 8 + 4);
                float4 n0 = *reinterpret_cast<const float4*>(Wn + d * 8);
                float4 n1 = *reinterpret_cast<const float4*>(Wn + d * 8 + 4);
                aB[0] = fmaf(xt, r0.x, aB[0]); aB[1] = fmaf(xt, r0.y, aB[1]);
                aB[2] = fmaf(xt, r0.z, aB[2]); aB[3] = fmaf(xt, r0.w, aB[3]);
                aB[4] = fmaf(xt, r1.x, aB[4]); aB[5] = fmaf(xt, r1.y, aB[5]);
                aB[6] = fmaf(xt, r1.z, aB[6]); aB[7] = fmaf(xt, r1.w, aB[7]);
                aN[0] = fmaf(xt, n0.x, aN[0]); aN[1] = fmaf(xt, n0.y, aN[1]);
                aN[2] = fmaf(xt, n0.z, aN[2]); aN[3] = fmaf(xt, n0.w, aN[3]);
                aN[4] = fmaf(xt, n1.x, aN[4]); aN[5] = fmaf(xt, n1.y, aN[5]);
                aN[6] = fmaf(xt, n1.z, aN[6]); aN[7] = fmaf(xt, n1.w, aN[7]);
            }
            #pragma unroll
            for (int m = 0; m < 8; m++) {
                #pragma unroll
                for (int off = 16; off > 0; off >>= 1) {
                    aB[m] += __shfl_down_sync(0xffffffffu, aB[m], off);
                    aN[m] += __shfl_down_sync(0xffffffffu, aN[m], off);
                }
            }
            if (lane == 0) {
                float pw[8];
                float mx = -1e30f;
                #pragma unroll
                for (int m = 0; m < 8; m++) {
                    float z  = aN[m] + bn[m];
                    float sp = (z > 20.f) ? z : log1pf(expf(z));
                    float l  = aB[m] + br[m] + noise[bb * 8 + m] * sp;
                    pw[m] = l;
                    if (l > mx) mx = l;
                }
                float s = 0.f;
                #pragma unroll
                for (int m = 0; m < 8; m++) { pw[m] = expf(pw[m] - mx); s += pw[m]; }
                float inv = 1.f / s;
                #pragma unroll
                for (int m = 0; m < 8; m++) pw[m] *= inv;

                unsigned kept = 0u;
                #pragma unroll
                for (int p = 0; p < 4; p++) {
                    float best = -1.f; int bi = 0;
                    #pragma unroll
                    for (int m = 0; m < 8; m++) {
                        bool free_m = ((kept >> m) & 1u) == 0u;
                        if (free_m && pw[m] > best) { best = pw[m]; bi = m; }
                    }
                    kept |= (1u << bi);
                }
                #pragma unroll
                for (int m = 0; m < 8; m++)
                    out[bb * 8 + m] = ((kept >> m) & 1u) ? pw[m] : 0.f;
            }
        }
        __syncthreads();
        if (tid == 0) g_arrive = 0u;   // reset for next launch/replay
    }
}

extern "C" void kernel_launch(void* const* d_in, const int* in_sizes, int n_in,
                              void* d_out, int out_size) {
    const float* x     = (const float*)d_in[0];
    const float* noise = (const float*)d_in[1];
    const float* Wr    = (const float*)d_in[2];
    const float* br    = (const float*)d_in[3];
    const float* Wn    = (const float*)d_in[4];
    const float* bn    = (const float*)d_in[5];
    const float* wt    = (const float*)d_in[6];
    const float* bt    = (const float*)d_in[7];
    const float* wl    = (const float*)d_in[8];
    const float* bl    = (const float*)d_in[9];
    float* out = (float*)d_out;

    (void)cudaFuncSetAttribute(msr_main, cudaFuncAttributeMaxDynamicSharedMemorySize,
                               (int)sizeof(Smem));
    dim3 grid(NTILES, Bb);
    msr_main<<<grid, NTH, sizeof(Smem)>>>(x, wt, bt, wl, bl,
                                          noise, Wr, br, Wn, bn, out);
}

// round 6
// speedup vs baseline: 1.1384x; 1.0012x over previous
#include <cuda_runtime.h>
#include <math.h>

namespace {

constexpr int T   = 512;
constexpr int D   = 512;
constexpr int Bb  = 16;
constexpr int DT  = 16;          // d-tile per CTA
constexpr int NTH = 256;
constexpr int NTILES = D / DT;   // 32
constexpr int NCTA = NTILES * Bb; // 512
constexpr int F   = 255;         // freq bins 1..255
constexpr float TWO_PI = 6.2831853071795864769f;

struct alignas(16) ULL2 { unsigned long long x, y; };

struct Smem {
    float  xs[T * DT];            // x, then x_rem (in place)
    float  cs[(T + 1) * DT];      // phase1: e[] (first 4096) + o[] (next 4096); phase3+: prefix sums
    float  scratch[T * DT];       // phase1: Re/Im (255*16 float2); phase2+: season
    float2 tab[T];                // (cos, sin)(2*pi*j/512)
    float  wl[T];                 // W_lin
    float  wt[8], bt[8];          // W_trend, b_trend (6 used)
    int    selk[DT][4];           // selected freq index k (1..255)
    float  selRe[DT][4];
    float  selIm[DT][4];
    float  xr0[DT], xrL[DT];      // x_rem at t=0 and t=T-1 (edge replication)
    float  red[NTH];
    int    done_flag;
};

__device__ float g_xtrans[Bb * D];
__device__ unsigned int g_arrive = 0;

} // namespace

#define FMA2(d, a, b, c) asm("fma.rn.f32x2 %0, %1, %2, %3;" : "=l"(d) : "l"(a), "l"(b), "l"(c))
#define PACK2(d, x)      asm("mov.b64 %0, {%1, %1};" : "=l"(d) : "f"(x))
#define PACK2二(d, lo, hi) asm("mov.b64 %0, {%1, %2};" : "=l"(d) : "f"(lo), "f"(hi))
#define UNPACK2(lo, hi, s) asm("mov.b64 {%0, %1}, %2;" : "=f"(lo), "=f"(hi) : "l"(s))

__global__ __launch_bounds__(NTH) void msr_main(
    const float* __restrict__ x,
    const float* __restrict__ wt_g,
    const float* __restrict__ bt_g,
    const float* __restrict__ wl_g,
    const float* __restrict__ bl_g,
    const float* __restrict__ noise,
    const float* __restrict__ Wr, const float* __restrict__ br,
    const float* __restrict__ Wn, const float* __restrict__ bn,
    float* __restrict__ out)
{
    extern __shared__ unsigned char smem_raw[];
    Smem& sm = *reinterpret_cast<Smem*>(smem_raw);

    const int tid = threadIdx.x;
    const int b   = blockIdx.y;
    const int d0  = blockIdx.x * DT;

    // ---- init tables ----
    for (int j = tid; j < T; j += NTH) {
        float s, c;
        sincosf(TWO_PI * (float)j / (float)T, &s, &c);
        sm.tab[j] = make_float2(c, s);
        sm.wl[j]  = wl_g[j];
    }
    if (tid < 6) { sm.wt[tid] = wt_g[tid]; sm.bt[tid] = bt_g[tid]; }

    // ---- load x tile: xs[t*DT + dd] = x[b, t, d0+dd] ----
    {
        const float* xb = x + (size_t)b * T * D + d0;
        const int q = (tid & 3) * 4;
        const int t0 = tid >> 2;
        #pragma unroll
        for (int i = 0; i < 8; i++) {
            int t = t0 + 64 * i;
            float4 v = *reinterpret_cast<const float4*>(xb + (size_t)t * D + q);
            *reinterpret_cast<float4*>(&sm.xs[t * DT + q]) = v;
        }
    }
    __syncthreads();

    // ---- Phase 1a: even/odd precompute (real-input symmetry) ----
    {
        float* ce = sm.cs;
        float* co = sm.cs + 4096;
        for (int idx = tid; idx < 255 * DT; idx += NTH) {
            int t = (idx >> 4) + 1, dd = idx & 15;
            float a  = sm.xs[t * DT + dd];
            float bb = sm.xs[(T - t) * DT + dd];
            ce[t * DT + dd] = a + bb;
            co[t * DT + dd] = a - bb;
        }
    }
    __syncthreads();

    // ---- Phase 1: half-range DFT with packed f32x2 FMA; thread owns f = tid+1 ----
    {
        const int f = tid + 1;
        const float* ce = sm.cs;
        const float* co = sm.cs + 4096;
        const float2 w = sm.tab[f & (T - 1)];
        const float cw = w.x, sw = w.y;
        unsigned long long accR2[8], accI2[8];
        const float sgn = (f & 1) ? -1.f : 1.f;
        #pragma unroll
        for (int q = 0; q < 8; q++) {
            float2 v0 = *reinterpret_cast<const float2*>(&sm.xs[0 * DT + q * 2]);
            float2 v2 = *reinterpret_cast<const float2*>(&sm.xs[256 * DT + q * 2]);
            float lo = fmaf(sgn, v2.x, v0.x);
            float hi = fmaf(sgn, v2.y, v0.y);
            PACK2二(accR2[q], lo, hi);
            accI2[q] = 0ull;
        }

        float cr = 1.f, si = 0.f;
        #pragma unroll 1
        for (int blk = 0; blk < 4; blk++) {
            const int tstart = (blk == 0) ? 1 : blk * 64;
            const int tend   = blk * 64 + 64;
            { float2 e = sm.tab[(f * tstart) & (T - 1)]; cr = e.x; si = e.y; }
            #pragma unroll 2
            for (int t = tstart; t < tend; t++) {
                unsigned long long cr2, nsi2;
                PACK2(cr2, cr);
                float nsi = -si;
                PACK2(nsi2, nsi);
                const ULL2* ep = reinterpret_cast<const ULL2*>(&ce[t * DT]);
                const ULL2* op = reinterpret_cast<const ULL2*>(&co[t * DT]);
                ULL2 e0 = ep[0], e1 = ep[1], e2 = ep[2], e3 = ep[3];
                ULL2 o0 = op[0], o1 = op[1], o2 = op[2], o3 = op[3];
                FMA2(accR2[0], e0.x, cr2, accR2[0]);  FMA2(accI2[0], o0.x, nsi2, accI2[0]);
                FMA2(accR2[1], e0.y, cr2, accR2[1]);  FMA2(accI2[1], o0.y, nsi2, accI2[1]);
                FMA2(accR2[2], e1.x, cr2, accR2[2]);  FMA2(accI2[2], o1.x, nsi2, accI2[2]);
                FMA2(accR2[3], e1.y, cr2, accR2[3]);  FMA2(accI2[3], o1.y, nsi2, accI2[3]);
                FMA2(accR2[4], e2.x, cr2, accR2[4]);  FMA2(accI2[4], o2.x, nsi2, accI2[4]);
                FMA2(accR2[5], e2.y, cr2, accR2[5]);  FMA2(accI2[5], o2.y, nsi2, accI2[5]);
                FMA2(accR2[6], e3.x, cr2, accR2[6]);  FMA2(accI2[6], o3.x, nsi2, accI2[6]);
                FMA2(accR2[7], e3.y, cr2, accR2[7]);  FMA2(accI2[7], o3.y, nsi2, accI2[7]);
                float c2 = cr * cw - si * sw;
                si = fmaf(si, cw, cr * sw);
                cr = c2;
            }
        }

        if (tid < F) {
            float2* ri = reinterpret_cast<float2*>(sm.scratch);
            #pragma unroll
            for (int q = 0; q < 8; q++) {
                float rlo, rhi, ilo, ihi;
                UNPACK2(rlo, rhi, accR2[q]);
                UNPACK2(ilo, ihi, accI2[q]);
                ri[tid * DT + q * 2 + 0] = make_float2(rlo, ilo);
                ri[tid * DT + q * 2 + 1] = make_float2(rhi, ihi);
            }
        }
    }
    __syncthreads();

    // ---- Phase 1b: per-d top-4 |X|^2 (tie -> lower index) ----
    {
        const int lane = tid & 31, wid = tid >> 5;
        const float2* ri = reinterpret_cast<const float2*>(sm.scratch);
        for (int dd = wid * 2; dd < wid * 2 + 2; dd++) {
            int sel0 = -1, sel1 = -1, sel2 = -1, sel3 = -1;
            #pragma unroll
            for (int pass = 0; pass < 4; pass++) {
                float best = -1.f; int bi = 0x7fffffff;
                for (int r = lane; r < F; r += 32) {
                    if (r == sel0 || r == sel1 || r == sel2 || r == sel3) continue;
                    float2 v = ri[r * DT + dd];
                    float a = v.x * v.x + v.y * v.y;
                    if (a > best || (a == best && r < bi)) { best = a; bi = r; }
                }
                #pragma unroll
                for (int off = 16; off > 0; off >>= 1) {
                    float ob = __shfl_down_sync(0xffffffffu, best, off);
                    int   oi = __shfl_down_sync(0xffffffffu, bi,   off);
                    if (ob > best || (ob == best && oi < bi)) { best = ob; bi = oi; }
                }
                bi = __shfl_sync(0xffffffffu, bi, 0);
                if      (pass == 0) sel0 = bi;
                else if (pass == 1) sel1 = bi;
                else if (pass == 2) sel2 = bi;
                else                sel3 = bi;
            }
            if (lane == 0) {
                int s4[4] = { sel0, sel1, sel2, sel3 };
                #pragma unroll
                for (int j = 0; j < 4; j++) {
                    int r = s4[j];
                    float2 v = ri[r * DT + dd];
                    sm.selk[dd][j]  = r + 1;
                    sm.selRe[dd][j] = v.x;
                    sm.selIm[dd][j] = v.y;
                }
            }
        }
    }
    __syncthreads();

    // ---- Phase 2: season, x_rem = x - season (in place), store season ----
    {
        const float scale = 2.0f / (float)T;
        for (int idx = tid; idx < T * DT; idx += NTH) {
            int t = idx >> 4, dd = idx & 15;
            float se = 0.f;
            #pragma unroll
            for (int j = 0; j < 4; j++) {
                int k = sm.selk[dd][j];
                float2 e = sm.tab[(k * t) & (T - 1)];
                se = fmaf(sm.selRe[dd][j], e.x, se);
                se = fmaf(-sm.selIm[dd][j], e.y, se);
            }
            se *= scale;
            float xr = sm.xs[idx] - se;
            sm.xs[idx] = xr;
            sm.scratch[idx] = se;
            if (t == 0)     sm.xr0[dd] = xr;
            if (t == T - 1) sm.xrL[dd] = xr;
        }
    }
    __syncthreads();

    // ---- Phase 3: segmented parallel prefix sums of x_rem per d ----
    {
        const int dd = tid & 15, seg = tid >> 4;
        const int t0 = seg * 32;
        float s = 0.f;
        #pragma unroll
        for (int i = 0; i < 32; i++) s += sm.xs[(t0 + i) * DT + dd];
        sm.red[seg * 16 + dd] = s;
    }
    __syncthreads();
    if (tid < 16) {
        float run = 0.f;
        #pragma unroll
        for (int sgi = 0; sgi < 16; sgi++) {
            float v = sm.red[sgi * 16 + tid];
            sm.red[sgi * 16 + tid] = run;
            run += v;
        }
    }
    __syncthreads();
    {
        const int dd = tid & 15, seg = tid >> 4;
        const int t0 = seg * 32;
        float run = sm.red[seg * 16 + dd];
        if (seg == 0) sm.cs[dd] = 0.f;
        #pragma unroll
        for (int i = 0; i < 32; i++) {
            run += sm.xs[(t0 + i) * DT + dd];
            sm.cs[(t0 + i + 1) * DT + dd] = run;
        }
    }
    __syncthreads();

    // ---- Phase 4: moving averages + softmax blend + W_lin reduction ----
    {
        const int dd = tid & 15;
        const float x0 = sm.xr0[dd], xL = sm.xrL[dd];
        float wtr[6], btr[6];
        #pragma unroll
        for (int j = 0; j < 6; j++) { wtr[j] = sm.wt[j]; btr[j] = sm.bt[j]; }

        float acc = 0.f;
        const int tb = tid >> 4;
        #pragma unroll 4
        for (int i = 0; i < 32; i++) {
            int t = tb + 16 * i;
            float xr = sm.xs[t * DT + dd];
            float num = 0.f, den = 0.f;
            const int ksArr[6] = { 4, 8, 12, 16, 24, 32 };
            #pragma unroll
            for (int j = 0; j < 6; j++) {
                const int k = ksArr[j];
                const int h = k >> 1;
                int lo = t - h, hi = t + h - 1;
                int hiC = hi < (T - 1) ? hi : (T - 1);
                int loC = lo > 0 ? lo : 0;
                float s = sm.cs[(hiC + 1) * DT + dd] - sm.cs[loC * DT + dd];
                if (lo < 0)     s = fmaf((float)(-lo), x0, s);
                if (hi > T - 1) s = fmaf((float)(hi - (T - 1)), xL, s);
                float e = __expf(fmaf(xr, wtr[j], btr[j]));
                den += e;
                num = fmaf(s * (1.0f / (float)k), e, num);
            }
            float xsum = xr + 2.f * sm.scratch[t * DT + dd] + num / den;
            acc = fmaf(xsum, sm.wl[t], acc);
        }
        sm.red[tid] = acc;
    }
    __syncthreads();

    if (tid < DT) {
        float s = 0.f;
        #pragma unroll
        for (int j = 0; j < NTH / DT; j++) s += sm.red[tid + DT * j];
        g_xtrans[b * D + d0 + tid] = s + bl_g[0];
        __threadfence();
    }
    __syncthreads();

    // ---- Fused finalize: last CTA does router head for all 16 b ----
    if (tid == 0) {
        unsigned int old = atomicAdd(&g_arrive, 1u);
        sm.done_flag = (old == (unsigned)(NCTA - 1)) ? 1 : 0;
    }
    __syncthreads();
    if (sm.done_flag) {
        __threadfence();
        const int lane = tid & 31, wid = tid >> 5;
        #pragma unroll 1
        for (int rep = 0; rep < 2; rep++) {
            const int bb = wid * 2 + rep;
            float aB[8], aN[8];
            #pragma unroll
            for (int m = 0; m < 8; m++) { aB[m] = 0.f; aN[m] = 0.f; }
            for (int d = lane; d < D; d += 32) {
                float xt = g_xtrans[bb * D + d];
                float4 r0 = *reinterpret_cast<const float4*>(Wr + d * 8);
                float4 r1 = *reinterpret_cast<const float4*>(Wr + d * 8 + 4);
                float4 n0 = *reinterpret_cast<const float4*>(Wn + d * 8);
                float4 n1 = *reinterpret_cast<const float4*>(Wn + d * 8 + 4);
                aB[0] = fmaf(xt, r0.x, aB[0]); aB[1] = fmaf(xt, r0.y, aB[1]);
                aB[2] = fmaf(xt, r0.z, aB[2]); aB[3] = fmaf(xt, r0.w, aB[3]);
                aB[4] = fmaf(xt, r1.x, aB[4]); aB[5] = fmaf(xt, r1.y, aB[5]);
                aB[6] = fmaf(xt, r1.z, aB[6]); aB[7] = fmaf(xt, r1.w, aB[7]);
                aN[0] = fmaf(xt, n0.x, aN[0]); aN[1] = fmaf(xt, n0.y, aN[1]);
                aN[2] = fmaf(xt, n0.z, aN[2]); aN[3] = fmaf(xt, n0.w, aN[3]);
                aN[4] = fmaf(xt, n1.x, aN[4]); aN[5] = fmaf(xt, n1.y, aN[5]);
                aN[6] = fmaf(xt, n1.z, aN[6]); aN[7] = fmaf(xt, n1.w, aN[7]);
            }
            #pragma unroll
            for (int m = 0; m < 8; m++) {
                #pragma unroll
                for (int off = 16; off > 0; off >>= 1) {
                    aB[m] += __shfl_down_sync(0xffffffffu, aB[m], off);
                    aN[m] += __shfl_down_sync(0xffffffffu, aN[m], off);
                }
            }
            if (lane == 0) {
                float pw[8];
                float mx = -1e30f;
                #pragma unroll
                for (int m = 0; m < 8; m++) {
                    float z  = aN[m] + bn[m];
                    float sp = (z > 20.f) ? z : log1pf(expf(z));
                    float l  = aB[m] + br[m] + noise[bb * 8 + m] * sp;
                    pw[m] = l;
                    if (l > mx) mx = l;
                }
                float s = 0.f;
                #pragma unroll
                for (int m = 0; m < 8; m++) { pw[m] = expf(pw[m] - mx); s += pw[m]; }
                float inv = 1.f / s;
                #pragma unroll
                for (int m = 0; m < 8; m++) pw[m] *= inv;

                unsigned kept = 0u;
                #pragma unroll
                for (int p = 0; p < 4; p++) {
                    float best = -1.f; int bi = 0;
                    #pragma unroll
                    for (int m = 0; m < 8; m++) {
                        bool free_m = ((kept >> m) & 1u) == 0u;
                        if (free_m && pw[m] > best) { best = pw[m]; bi = m; }
                    }
                    kept |= (1u << bi);
                }
                #pragma unroll
                for (int m = 0; m < 8; m++)
                    out[bb * 8 + m] = ((kept >> m) & 1u) ? pw[m] : 0.f;
            }
        }
        __syncthreads();
        if (tid == 0) g_arrive = 0u;   // reset for next launch/replay
    }
}

extern "C" void kernel_launch(void* const* d_in, const int* in_sizes, int n_in,
                              void* d_out, int out_size) {
    const float* x     = (const float*)d_in[0];
    const float* noise = (const float*)d_in[1];
    const float* Wr    = (const float*)d_in[2];
    const float* br    = (const float*)d_in[3];
    const float* Wn    = (const float*)d_in[4];
    const float* bn    = (const float*)d_in[5];
    const float* wt    = (const float*)d_in[6];
    const float* bt    = (const float*)d_in[7];
    const float* wl    = (const float*)d_in[8];
    const float* bl    = (const float*)d_in[9];
    float* out = (float*)d_out;

    (void)cudaFuncSetAttribute(msr_main, cudaFuncAttributeMaxDynamicSharedMemorySize,
                               (int)sizeof(Smem));
    dim3 grid(NTILES, Bb);
    msr_main<<<grid, NTH, sizeof(Smem)>>>(x, wt, bt, wl, bl,
                                          noise, Wr, br, Wn, bn, out);
}

// round 8
// speedup vs baseline: 1.4714x; 1.2925x over previous
#include <cuda_runtime.h>
#include <math.h>

namespace {

constexpr int T   = 512;
constexpr int D   = 512;
constexpr int Bb  = 16;
constexpr int DT  = 16;          // d-tile per CTA
constexpr int NTH = 256;
constexpr int NTILES = D / DT;   // 32
constexpr int NCTA = NTILES * Bb; // 512
constexpr int F   = 255;         // freq bins 1..255
constexpr float TWO_PI = 6.2831853071795864769f;
constexpr float SSCALE = 2.0f / (float)T;     // season scale
constexpr float SSCALE2 = 4.0f / (float)T;    // 2 * season scale

struct alignas(16) ULL2 { unsigned long long x, y; };

struct Smem {
    float  bufB[8224];    // phase1: e[t*16+dd] (t=1..255) @0, o @+4096; phase3+: cs prefix (513*16)
    float  scratch[8192]; // x (load) -> Re/Im (255*16 float2) -> x_rem (512*16)
    float2 tab[T];        // (cos, sin)(2*pi*j/512)
    float  wl[T];         // W_lin
    float  wt[8], bt[8];  // W_trend, b_trend (6 used)
    int    selk[DT][4];   // selected freq index k (1..255)
    float  selRe[DT][4];
    float  selIm[DT][4];
    float  x0row[DT], x256row[DT];
    float  xr0[DT], xrL[DT];
    float  red[NTH];
    int    done_flag;
};

__device__ float g_xtrans[Bb * D];
__device__ unsigned int g_arrive = 0;

} // namespace

#define FMA2(d, a, b, c) asm("fma.rn.f32x2 %0, %1, %2, %3;" : "=l"(d) : "l"(a), "l"(b), "l"(c))
#define PACK2(d, x)      asm("mov.b64 %0, {%1, %1};" : "=l"(d) : "f"(x))
#define PACK2P(d, lo, hi) asm("mov.b64 %0, {%1, %2};" : "=l"(d) : "f"(lo), "f"(hi))
#define UNPACK2(lo, hi, s) asm("mov.b64 {%0, %1}, %2;" : "=f"(lo), "=f"(hi) : "l"(s))

__global__ __launch_bounds__(NTH, 3) void msr_main(
    const float* __restrict__ x,
    const float* __restrict__ wt_g,
    const float* __restrict__ bt_g,
    const float* __restrict__ wl_g,
    const float* __restrict__ bl_g,
    const float* __restrict__ noise,
    const float* __restrict__ Wr, const float* __restrict__ br,
    const float* __restrict__ Wn, const float* __restrict__ bn,
    float* __restrict__ out)
{
    extern __shared__ unsigned char smem_raw[];
    Smem& sm = *reinterpret_cast<Smem*>(smem_raw);

    const int tid = threadIdx.x;
    const int b   = blockIdx.y;
    const int d0  = blockIdx.x * DT;

    // ---- init tables ----
    for (int j = tid; j < T; j += NTH) {
        float s, c;
        sincosf(TWO_PI * (float)j / (float)T, &s, &c);
        sm.tab[j] = make_float2(c, s);
        sm.wl[j]  = wl_g[j];
    }
    if (tid < 6) { sm.wt[tid] = wt_g[tid]; sm.bt[tid] = bt_g[tid]; }

    // ---- load x tile into scratch: scratch[t*16 + dd] = x[b, t, d0+dd] ----
    {
        const float* xb = x + (size_t)b * T * D + d0;
        const int q = (tid & 3) * 4;
        const int t0 = tid >> 2;
        #pragma unroll
        for (int i = 0; i < 8; i++) {
            int t = t0 + 64 * i;
            float4 v = *reinterpret_cast<const float4*>(xb + (size_t)t * D + q);
            *reinterpret_cast<float4*>(&sm.scratch[t * DT + q]) = v;
        }
    }
    __syncthreads();

    // ---- Phase 1a: even/odd precompute e[t]=x[t]+x[512-t], o[t]=x[t]-x[512-t] ----
    {
        for (int idx = tid; idx < 255 * DT; idx += NTH) {
            int t = (idx >> 4) + 1, dd = idx & 15;
            float a  = sm.scratch[t * DT + dd];
            float bb = sm.scratch[(T - t) * DT + dd];
            sm.bufB[t * DT + dd]        = a + bb;
            sm.bufB[4096 + t * DT + dd] = a - bb;
        }
        if (tid < DT) {
            sm.x0row[tid]   = sm.scratch[tid];
            sm.x256row[tid] = sm.scratch[256 * DT + tid];
        }
    }
    __syncthreads();

    // ---- Phase 1: half-range DFT, thread owns freqs (fi, fi+128), 8 d's ----
    {
        const int fi   = (tid & 127) + 1;    // 1..128
        const int doff = (tid >> 7) * 8;     // 0 or 8
        const float* ce = sm.bufB;
        const float* co = sm.bufB + 4096;

        unsigned long long aAR[4], aAI[4], aBR[4], aBI[4];
        const float sgn = (fi & 1) ? -1.f : 1.f;   // (-1)^fi = (-1)^(fi+128)
        #pragma unroll
        for (int q = 0; q < 4; q++) {
            float2 v0 = *reinterpret_cast<const float2*>(&sm.x0row[doff + q * 2]);
            float2 v2 = *reinterpret_cast<const float2*>(&sm.x256row[doff + q * 2]);
            float lo = fmaf(sgn, v2.x, v0.x);
            float hi = fmaf(sgn, v2.y, v0.y);
            PACK2P(aAR[q], lo, hi);
            aBR[q] = aAR[q];
            aAI[q] = 0ull; aBI[q] = 0ull;
        }

        // peel t = 1..3 (exact table twiddles for both freqs)
        #pragma unroll
        for (int t = 1; t <= 3; t++) {
            float2 ea = sm.tab[(fi * t) & (T - 1)];
            float2 eb = sm.tab[((fi + 128) * t) & (T - 1)];
            unsigned long long cA2, nsA2, cB2, nsB2;
            float na = -ea.y, nb = -eb.y;
            PACK2(cA2, ea.x); PACK2(nsA2, na);
            PACK2(cB2, eb.x); PACK2(nsB2, nb);
            const ULL2* ep = reinterpret_cast<const ULL2*>(&ce[t * DT + doff]);
            const ULL2* op = reinterpret_cast<const ULL2*>(&co[t * DT + doff]);
            ULL2 e0 = ep[0], e1 = ep[1];
            ULL2 o0 = op[0], o1 = op[1];
            FMA2(aAR[0], e0.x, cA2, aAR[0]); FMA2(aAR[1], e0.y, cA2, aAR[1]);
            FMA2(aAR[2], e1.x, cA2, aAR[2]); FMA2(aAR[3], e1.y, cA2, aAR[3]);
            FMA2(aAI[0], o0.x, nsA2, aAI[0]); FMA2(aAI[1], o0.y, nsA2, aAI[1]);
            FMA2(aAI[2], o1.x, nsA2, aAI[2]); FMA2(aAI[3], o1.y, nsA2, aAI[3]);
            FMA2(aBR[0], e0.x, cB2, aBR[0]); FMA2(aBR[1], e0.y, cB2, aBR[1]);
            FMA2(aBR[2], e1.x, cB2, aBR[2]); FMA2(aBR[3], e1.y, cB2, aBR[3]);
            FMA2(aBI[0], o0.x, nsB2, aBI[0]); FMA2(aBI[1], o0.y, nsB2, aBI[1]);
            FMA2(aBI[2], o1.x, nsB2, aBI[2]); FMA2(aBI[3], o1.y, nsB2, aBI[3]);
        }

        // main loop t = 4..255 in unroll-4 groups; freq B twiddle = A twiddle * i^t
        const float2 w = sm.tab[fi];
        const float cw = w.x, sw = w.y;
        float cr = 1.f, si = 0.f;
        #pragma unroll 1
        for (int g = 0; g < 63; g++) {
            const int t0 = 4 + g * 4;
            if ((t0 & 63) == 4) {                // resync from exact table
                float2 e = sm.tab[(fi * t0) & (T - 1)];
                cr = e.x; si = e.y;
            }
            #pragma unroll
            for (int j = 0; j < 4; j++) {
                const int t = t0 + j;
                unsigned long long c2, s2, nc2, ns2;
                float nc = -cr, ns = -si;
                PACK2(c2, cr); PACK2(s2, si);
                PACK2(nc2, nc); PACK2(ns2, ns);
                const ULL2* ep = reinterpret_cast<const ULL2*>(&ce[t * DT + doff]);
                const ULL2* op = reinterpret_cast<const ULL2*>(&co[t * DT + doff]);
                ULL2 e0 = ep[0], e1 = ep[1];
                ULL2 o0 = op[0], o1 = op[1];
                // freq A: cos=c, -sin=-s
                FMA2(aAR[0], e0.x, c2, aAR[0]); FMA2(aAR[1], e0.y, c2, aAR[1]);
                FMA2(aAR[2], e1.x, c2, aAR[2]); FMA2(aAR[3], e1.y, c2, aAR[3]);
                FMA2(aAI[0], o0.x, ns2, aAI[0]); FMA2(aAI[1], o0.y, ns2, aAI[1]);
                FMA2(aAI[2], o1.x, ns2, aAI[2]); FMA2(aAI[3], o1.y, ns2, aAI[3]);
                // freq B = A rotated by i^t (t mod 4 == j):
                //  j=0: cB=c,  -sB=-s ; j=1: cB=-s, -sB=-c
                //  j=2: cB=-c, -sB=+s ; j=3: cB=+s, -sB=+c
                unsigned long long cB2  = (j == 0) ? c2  : (j == 1) ? ns2 : (j == 2) ? nc2 : s2;
                unsigned long long nsB2 = (j == 0) ? ns2 : (j == 1) ? nc2 : (j == 2) ? s2  : c2;
                FMA2(aBR[0], e0.x, cB2, aBR[0]); FMA2(aBR[1], e0.y, cB2, aBR[1]);
                FMA2(aBR[2], e1.x, cB2, aBR[2]); FMA2(aBR[3], e1.y, cB2, aBR[3]);
                FMA2(aBI[0], o0.x, nsB2, aBI[0]); FMA2(aBI[1], o0.y, nsB2, aBI[1]);
                FMA2(aBI[2], o1.x, nsB2, aBI[2]); FMA2(aBI[3], o1.y, nsB2, aBI[3]);
                // advance twiddle by one step
                float cn = cr * cw - si * sw;
                si = fmaf(si, cw, cr * sw);
                cr = cn;
            }
        }

        // write Re/Im into scratch (x is dead; x0/x256 saved)
        float2* ri = reinterpret_cast<float2*>(sm.scratch);
        #pragma unroll
        for (int q = 0; q < 4; q++) {
            float rlo, rhi, ilo, ihi;
            UNPACK2(rlo, rhi, aAR[q]);
            UNPACK2(ilo, ihi, aAI[q]);
            ri[(fi - 1) * DT + doff + q * 2 + 0] = make_float2(rlo, ilo);
            ri[(fi - 1) * DT + doff + q * 2 + 1] = make_float2(rhi, ihi);
        }
        if (fi <= 127) {           // B = fi+128 in 129..255 (fi=128 -> Nyquist, discard)
            #pragma unroll
            for (int q = 0; q < 4; q++) {
                float rlo, rhi, ilo, ihi;
                UNPACK2(rlo, rhi, aBR[q]);
                UNPACK2(ilo, ihi, aBI[q]);
                ri[(fi + 127) * DT + doff + q * 2 + 0] = make_float2(rlo, ilo);
                ri[(fi + 127) * DT + doff + q * 2 + 1] = make_float2(rhi, ihi);
            }
        }
    }
    __syncthreads();

    // ---- Phase 1b: per-d top-4 |X|^2 (tie -> lower index) ----
    {
        const int lane = tid & 31, wid = tid >> 5;
        const float2* ri = reinterpret_cast<const float2*>(sm.scratch);
        for (int dd = wid * 2; dd < wid * 2 + 2; dd++) {
            int sel0 = -1, sel1 = -1, sel2 = -1, sel3 = -1;
            #pragma unroll
            for (int pass = 0; pass < 4; pass++) {
                float best = -1.f; int bi = 0x7fffffff;
                for (int r = lane; r < F; r += 32) {
                    if (r == sel0 || r == sel1 || r == sel2 || r == sel3) continue;
                    float2 v = ri[r * DT + dd];
                    float a = v.x * v.x + v.y * v.y;
                    if (a > best || (a == best && r < bi)) { best = a; bi = r; }
                }
                #pragma unroll
                for (int off = 16; off > 0; off >>= 1) {
                    float ob = __shfl_down_sync(0xffffffffu, best, off);
                    int   oi = __shfl_down_sync(0xffffffffu, bi,   off);
                    if (ob > best || (ob == best && oi < bi)) { best = ob; bi = oi; }
                }
                bi = __shfl_sync(0xffffffffu, bi, 0);
                if      (pass == 0) sel0 = bi;
                else if (pass == 1) sel1 = bi;
                else if (pass == 2) sel2 = bi;
                else                sel3 = bi;
            }
            if (lane == 0) {
                int s4[4] = { sel0, sel1, sel2, sel3 };
                #pragma unroll
                for (int j = 0; j < 4; j++) {
                    int r = s4[j];
                    float2 v = ri[r * DT + dd];
                    sm.selk[dd][j]  = r + 1;
                    sm.selRe[dd][j] = v.x;
                    sm.selIm[dd][j] = v.y;
                }
            }
        }
    }
    __syncthreads();

    // ---- Phase 2: reconstruct x from e/o, compute x_rem pairwise into scratch ----
    {
        for (int idx = tid; idx < 255 * DT; idx += NTH) {
            int t = (idx >> 4) + 1, dd = idx & 15;
            float e = sm.bufB[t * DT + dd];
            float o = sm.bufB[4096 + t * DT + dd];
            float xt = 0.5f * (e + o);           // x[t]
            float xm = 0.5f * (e - o);           // x[512-t]
            float seP = 0.f, seM = 0.f;
            #pragma unroll
            for (int j = 0; j < 4; j++) {
                int k = sm.selk[dd][j];
                float2 wv = sm.tab[(k * t) & (T - 1)];
                float a  = sm.selRe[dd][j] * wv.x;
                float bq = sm.selIm[dd][j] * wv.y;
                seP += a - bq;                   // season at t
                seM += a + bq;                   // season at 512-t (cos even, sin odd)
            }
            float xrt = xt - SSCALE * seP;
            float xrm = xm - SSCALE * seM;
            sm.scratch[t * DT + dd]       = xrt;
            sm.scratch[(T - t) * DT + dd] = xrm;
            if (t == 1) sm.xrL[dd] = xrm;        // t = 511
        }
        if (tid < 32) {
            int dd = tid & 15;
            if (tid < 16) {                      // t = 0
                float se = 0.f;
                #pragma unroll
                for (int j = 0; j < 4; j++) se += sm.selRe[dd][j];
                float xr = sm.x0row[dd] - SSCALE * se;
                sm.scratch[dd] = xr;
                sm.xr0[dd] = xr;
            } else {                             // t = 256: cos(pi k) = (-1)^k
                float se = 0.f;
                #pragma unroll
                for (int j = 0; j < 4; j++) {
                    float v = sm.selRe[dd][j];
                    se += (sm.selk[dd][j] & 1) ? -v : v;
                }
                sm.scratch[256 * DT + dd] = sm.x256row[dd] - SSCALE * se;
            }
        }
    }
    __syncthreads();

    // ---- Phase 3: segmented parallel prefix sums of x_rem -> cs in bufB ----
    {
        const int dd = tid & 15, seg = tid >> 4;
        const int t0 = seg * 32;
        float s = 0.f;
        #pragma unroll
        for (int i = 0; i < 32; i++) s += sm.scratch[(t0 + i) * DT + dd];
        sm.red[seg * 16 + dd] = s;
    }
    __syncthreads();
    if (tid < 16) {
        float run = 0.f;
        #pragma unroll
        for (int sgi = 0; sgi < 16; sgi++) {
            float v = sm.red[sgi * 16 + tid];
            sm.red[sgi * 16 + tid] = run;
            run += v;
        }
    }
    __syncthreads();
    {
        const int dd = tid & 15, seg = tid >> 4;
        const int t0 = seg * 32;
        float run = sm.red[seg * 16 + dd];
        if (seg == 0) sm.bufB[dd] = 0.f;
        #pragma unroll
        for (int i = 0; i < 32; i++) {
            run += sm.scratch[(t0 + i) * DT + dd];
            sm.bufB[(t0 + i + 1) * DT + dd] = run;
        }
    }
    __syncthreads();

    // ---- Phase 4: moving averages + softmax blend + recomputed season + W_lin ----
    {
        const int dd = tid & 15;
        const float x0 = sm.xr0[dd], xL = sm.xrL[dd];
        float wtr[6], btr[6];
        #pragma unroll
        for (int j = 0; j < 6; j++) { wtr[j] = sm.wt[j]; btr[j] = sm.bt[j]; }
        int   kk[4];
        float kre[4], kim[4];
        #pragma unroll
        for (int j = 0; j < 4; j++) {
            kk[j] = sm.selk[dd][j]; kre[j] = sm.selRe[dd][j]; kim[j] = sm.selIm[dd][j];
        }

        float acc = 0.f;
        const int tb = tid >> 4;
        const float* cs = sm.bufB;
        #pragma unroll 4
        for (int i = 0; i < 32; i++) {
            int t = tb + 16 * i;
            float xr = sm.scratch[t * DT + dd];
            float num = 0.f, den = 0.f;
            const int ksArr[6] = { 4, 8, 12, 16, 24, 32 };
            #pragma unroll
            for (int j = 0; j < 6; j++) {
                const int k = ksArr[j];
                const int h = k >> 1;
                int lo = t - h, hi = t + h - 1;
                int hiC = hi < (T - 1) ? hi : (T - 1);
                int loC = lo > 0 ? lo : 0;
                float s = cs[(hiC + 1) * DT + dd] - cs[loC * DT + dd];
                if (lo < 0)     s = fmaf((float)(-lo), x0, s);
                if (hi > T - 1) s = fmaf((float)(hi - (T - 1)), xL, s);
                float e = __expf(fmaf(xr, wtr[j], btr[j]));
                den += e;
                num = fmaf(s * (1.0f / (float)k), e, num);
            }
            float se = 0.f;
            #pragma unroll
            for (int j = 0; j < 4; j++) {
                float2 wv = sm.tab[(kk[j] * t) & (T - 1)];
                se = fmaf(kre[j], wv.x, se);
                se = fmaf(-kim[j], wv.y, se);
            }
            float xsum = xr + SSCALE2 * se + num / den;
            acc = fmaf(xsum, sm.wl[t], acc);
        }
        sm.red[tid] = acc;
    }
    __syncthreads();

    if (tid < DT) {
        float s = 0.f;
        #pragma unroll
        for (int j = 0; j < NTH / DT; j++) s += sm.red[tid + DT * j];
        g_xtrans[b * D + d0 + tid] = s + bl_g[0];
        __threadfence();
    }
    __syncthreads();

    // ---- Fused finalize: last CTA does router head for all 16 b ----
    if (tid == 0) {
        unsigned int old = atomicAdd(&g_arrive, 1u);
        sm.done_flag = (old == (unsigned)(NCTA - 1)) ? 1 : 0;
    }
    __syncthreads();
    if (sm.done_flag) {
        __threadfence();
        const int lane = tid & 31, wid = tid >> 5;
        #pragma unroll 1
        for (int rep = 0; rep < 2; rep++) {
            const int bb = wid * 2 + rep;
            float aB[8], aN[8];
            #pragma unroll
            for (int m = 0; m < 8; m++) { aB[m] = 0.f; aN[m] = 0.f; }
            for (int d = lane; d < D; d += 32) {
                float xt = g_xtrans[bb * D + d];
                float4 r0 = *reinterpret_cast<const float4*>(Wr + d * 8);
                float4 r1 = *reinterpret_cast<const float4*>(Wr + d * 8 + 4);
                float4 n0 = *reinterpret_cast<const float4*>(Wn + d * 8);
                float4 n1 = *reinterpret_cast<const float4*>(Wn + d * 8 + 4);
                aB[0] = fmaf(xt, r0.x, aB[0]); aB[1] = fmaf(xt, r0.y, aB[1]);
                aB[2] = fmaf(xt, r0.z, aB[2]); aB[3] = fmaf(xt, r0.w, aB[3]);
                aB[4] = fmaf(xt, r1.x, aB[4]); aB[5] = fmaf(xt, r1.y, aB[5]);
                aB[6] = fmaf(xt, r1.z, aB[6]); aB[7] = fmaf(xt, r1.w, aB[7]);
                aN[0] = fmaf(xt, n0.x, aN[0]); aN[1] = fmaf(xt, n0.y, aN[1]);
                aN[2] = fmaf(xt, n0.z, aN[2]); aN[3] = fmaf(xt, n0.w, aN[3]);
                aN[4] = fmaf(xt, n1.x, aN[4]); aN[5] = fmaf(xt, n1.y, aN[5]);
                aN[6] = fmaf(xt, n1.z, aN[6]); aN[7] = fmaf(xt, n1.w, aN[7]);
            }
            #pragma unroll
            for (int m = 0; m < 8; m++) {
                #pragma unroll
                for (int off = 16; off > 0; off >>= 1) {
                    aB[m] += __shfl_down_sync(0xffffffffu, aB[m], off);
                    aN[m] += __shfl_down_sync(0xffffffffu, aN[m], off);
                }
            }
            if (lane == 0) {
                float pw[8];
                float mx = -1e30f;
                #pragma unroll
                for (int m = 0; m < 8; m++) {
                    float z  = aN[m] + bn[m];
                    float sp = (z > 20.f) ? z : log1pf(expf(z));
                    float l  = aB[m] + br[m] + noise[bb * 8 + m] * sp;
                    pw[m] = l;
                    if (l > mx) mx = l;
                }
                float s = 0.f;
                #pragma unroll
                for (int m = 0; m < 8; m++) { pw[m] = expf(pw[m] - mx); s += pw[m]; }
                float inv = 1.f / s;
                #pragma unroll
                for (int m = 0; m < 8; m++) pw[m] *= inv;

                unsigned kept = 0u;
                #pragma unroll
                for (int p = 0; p < 4; p++) {
                    float best = -1.f; int bi = 0;
                    #pragma unroll
                    for (int m = 0; m < 8; m++) {
                        bool free_m = ((kept >> m) & 1u) == 0u;
                        if (free_m && pw[m] > best) { best = pw[m]; bi = m; }
                    }
                    kept |= (1u << bi);
                }
                #pragma unroll
                for (int m = 0; m < 8; m++)
                    out[bb * 8 + m] = ((kept >> m) & 1u) ? pw[m] : 0.f;
            }
        }
        __syncthreads();
        if (tid == 0) g_arrive = 0u;   // reset for next launch/replay
    }
}

extern "C" void kernel_launch(void* const* d_in, const int* in_sizes, int n_in,
                              void* d_out, int out_size) {
    const float* x     = (const float*)d_in[0];
    const float* noise = (const float*)d_in[1];
    const float* Wr    = (const float*)d_in[2];
    const float* br    = (const float*)d_in[3];
    const float* Wn    = (const float*)d_in[4];
    const float* bn    = (const float*)d_in[5];
    const float* wt    = (const float*)d_in[6];
    const float* bt    = (const float*)d_in[7];
    const float* wl    = (const float*)d_in[8];
    const float* bl    = (const float*)d_in[9];
    float* out = (float*)d_out;

    (void)cudaFuncSetAttribute(msr_main, cudaFuncAttributeMaxDynamicSharedMemorySize,
                               (int)sizeof(Smem));
    dim3 grid(NTILES, Bb);
    msr_main<<<grid, NTH, sizeof(Smem)>>>(x, wt, bt, wl, bl,
                                          noise, Wr, br, Wn, bn, out);
}